// round 16
// baseline (speedup 1.0000x reference)
#include <cuda_runtime.h>
#include <cuda_fp16.h>
#include <cstdint>
#include <math.h>

#define CHN 256
#define TDIM 4096
#define BATCH 16
#define SKIPOFF ((size_t)BATCH*CHN*TDIM)

// single fp16 planes (device globals: allocation-free)
__device__ __half g_x[(size_t)BATCH*4104*CHN];
__device__ __half g_z[(size_t)BATCH*TDIM*CHN];
__device__ __half g_w1[4*128*512];
__device__ __half g_w2[4*128*256];

// A persistent buffers (pitch 528 B) + B-only stage rings (128 rows x 80B) + bias
#define APITCH  528
#define P1_ABUF 38016            // 72 rows
#define P2_ABUF 33792            // 64 rows
#define BSTG    10240
#define P1_BIAS (P1_ABUF + 3*BSTG)       // 68736
#define P2_BIAS (P2_ABUF + 4*BSTG)       // 74752
#define P1_SMEM (P1_BIAS + 512)          // 69248, ring 3, 3 CTAs/SM
#define P2_SMEM (P2_BIAS + 512)          // 75264, ring 4; C staging reuses front

// ---------------- helpers ----------------
__device__ __forceinline__ uint32_t smem_u32(const void* p) {
    uint32_t a; asm("{ .reg .u64 t; cvta.to.shared.u64 t, %1; cvt.u32.u64 %0, t; }" : "=r"(a) : "l"(p));
    return a;
}
__device__ __forceinline__ void cp16(uint32_t d, const void* s) {
    asm volatile("cp.async.cg.shared.global [%0], [%1], 16;" :: "r"(d), "l"(s));
}
__device__ __forceinline__ void ldmx4(uint32_t* r, uint32_t a) {
    asm volatile("ldmatrix.sync.aligned.m8n8.x4.shared.b16 {%0,%1,%2,%3}, [%4];"
        : "=r"(r[0]), "=r"(r[1]), "=r"(r[2]), "=r"(r[3]) : "r"(a));
}
__device__ __forceinline__ void mma_h(float* d, const uint32_t* a, const uint32_t* b) {
    asm volatile("mma.sync.aligned.m16n8k16.row.col.f32.f16.f16.f32 "
        "{%0,%1,%2,%3}, {%4,%5,%6,%7}, {%8,%9}, {%0,%1,%2,%3};"
        : "+f"(d[0]), "+f"(d[1]), "+f"(d[2]), "+f"(d[3])
        : "r"(a[0]), "r"(a[1]), "r"(a[2]), "r"(a[3]), "r"(b[0]), "r"(b[1]));
}
__device__ __forceinline__ float gatedact(float f, float g) {
    float ef = __expf(2.0f * f);
    float tf = __fdividef(ef - 1.0f, ef + 1.0f);
    float sg = __fdividef(1.0f, 1.0f + __expf(-g));
    return tf * sg;
}

// ---------------------------------------------------------------------------
// Merged packing. Blocks [0,1536): weights; [1536,1536+4096): x plane (64-t tiles).
// g_w1[nb][n'][k]: n'<64 filter ch nb*64+n', n'>=64 gate;
//   k<256 -> tap1 (pairs x[t]), k>=256 -> tap0 (pairs x[t-8]).
// g_w2[nb][n'][k]: n'<64 res, else skip.
// g_x: [b][r=t+8][256] fp16 (rows 0-7 zero).
// ---------------------------------------------------------------------------
__global__ void pack_all_kernel(const float* __restrict__ x,
                                const float* __restrict__ wf, const float* __restrict__ wg,
                                const float* __restrict__ wr, const float* __restrict__ wsk)
{
    int bid = blockIdx.x, tid = threadIdx.x;
    if (bid < 1536) {
        int idx = bid * 256 + tid;
        if (idx < 262144) {
            int nb = idx >> 16, np = (idx >> 9) & 127, k = idx & 511;
            int o = nb * 64 + (np & 63), c = k & 255;
            const float* w = (np < 64) ? wf : wg;
            g_w1[idx] = __float2half_rn(w[o * 512 + c * 2 + ((k < 256) ? 1 : 0)]);
        } else {
            int j = idx - 262144;
            int nb = j >> 15, np = (j >> 8) & 127, k = j & 255;
            int o = nb * 64 + (np & 63);
            g_w2[j] = __float2half_rn((np < 64) ? wr[o * 256 + k] : wsk[o * 256 + k]);
        }
        return;
    }
    __shared__ float st[64][65];
    int bp = bid - 1536;
    int tc = bp & 63, cc = (bp >> 6) & 3, b = bp >> 8;
    for (int i = tid; i < 64 * 16; i += 256) {
        int c = i >> 4, q = i & 15;
        float4 v = *(const float4*)(x + ((size_t)(b * CHN + cc * 64 + c)) * TDIM + tc * 64 + q * 4);
        st[q*4+0][c] = v.x; st[q*4+1][c] = v.y; st[q*4+2][c] = v.z; st[q*4+3][c] = v.w;
    }
    __syncthreads();
    for (int i = tid; i < 64 * 32; i += 256) {
        int r = i >> 5, cp = (i & 31) * 2;
        __half h0 = __float2half_rn(st[r][cp]), h1 = __float2half_rn(st[r][cp + 1]);
        size_t go = ((size_t)b * 4104 + tc * 64 + 8 + r) * CHN + cc * 64 + cp;
        *(uint32_t*)(g_x + go) = ((uint32_t)__half_as_ushort(h1) << 16) | __half_as_ushort(h0);
    }
    if (tc == 0)
        for (int i = tid; i < 8 * 32; i += 256) {
            int r = i >> 5, cp = (i & 31) * 2;
            *(uint32_t*)(g_x + ((size_t)b * 4104 + r) * CHN + cc * 64 + cp) = 0;
        }
}

// ---------------------------------------------------------------------------
// PHASE 1: C[64 t][128 n(f|g)], K=512. A persistent (72 rows, taps via +8 row
// offset). B-only 3-stage ring. Bias staged in smem. In-register f/g pairing.
// ---------------------------------------------------------------------------
__global__ void __launch_bounds__(256, 3) gemm_p1(
    const float* __restrict__ b0v, const float* __restrict__ b1v)
{
    extern __shared__ unsigned char smraw[];
    const uint32_t sb = smem_u32(smraw);
    const int tid = threadIdx.x, lane = tid & 31, wid = tid >> 5;
    const int wm = wid & 1, wn = wid >> 1;
    const int tt = blockIdx.x, nb = blockIdx.y, b = blockIdx.z;
    const int t0 = tt * 64;

    const __half* Ap = g_x + (size_t)b * 4104 * CHN;
    const __half* Bw = g_w1 + nb * 128 * 512;
    float* sbias = (float*)(smraw + P1_BIAS);

    if (tid < 128)
        sbias[tid] = (tid < 64) ? __ldg(b0v + nb * 64 + tid)
                                : __ldg(b1v + nb * 64 + tid - 64);

    float acc[2][4][4];
    #pragma unroll
    for (int mi = 0; mi < 2; mi++)
        #pragma unroll
        for (int ni = 0; ni < 4; ni++)
            #pragma unroll
            for (int j = 0; j < 4; j++) acc[mi][ni][j] = 0.0f;

    // ---- persistent A load: 72 rows x 32 chunks ----
    for (int i = tid; i < 72 * 32; i += 256) {
        int r = i >> 5, seg = i & 31;
        cp16(sb + r * APITCH + seg * 16, Ap + (size_t)(t0 + r) * CHN + seg * 8);
    }
    asm volatile("cp.async.commit_group;" ::: "memory");

    auto load_stage = [&](int kc, int stg) {
        uint32_t sbase = sb + P1_ABUF + stg * BSTG;
        #pragma unroll
        for (int i = 0; i < 2; i++) {
            int idx = tid + i * 256;
            int r = idx >> 2, seg = idx & 3;
            cp16(sbase + r * 80 + seg * 16, Bw + (size_t)r * 512 + kc * 32 + seg * 8);
        }
        asm volatile("cp.async.commit_group;" ::: "memory");
    };

    load_stage(0, 0);
    load_stage(1, 1);

    int stg = 0;
    for (int kc = 0; kc < 16; kc++) {
        if (kc < 15) asm volatile("cp.async.wait_group 1;" ::: "memory");
        else         asm volatile("cp.async.wait_group 0;" ::: "memory");
        __syncthreads();
        if (kc + 2 < 16) {
            int nstg = stg + 2; if (nstg >= 3) nstg -= 3;
            load_stage(kc + 2, nstg);
        }

        const int koff = (kc < 8) ? 8 : 0;       // tap: x[t] (+8) vs x[t-8]
        const int acolb = (kc & 7) * 64;
        const uint32_t bbase = sb + P1_ABUF + stg * BSTG;
        #pragma unroll
        for (int ks = 0; ks < 2; ks++) {
            uint32_t ah[2][4], bf2[4][2];
            const int arow = lane & 15, acoll = ks * 16 + (lane >> 4) * 8;
            const int brow = (lane & 7) + ((lane >> 4) << 3);
            const int bcol = ks * 16 + ((lane >> 3) & 1) * 8;
            #pragma unroll
            for (int ni2 = 0; ni2 < 2; ni2++) {
                int nbase = ni2 * 64 + wn * 16;   // f rows / g rows
                uint32_t t4[4];
                ldmx4(t4, bbase + (nbase + brow) * 80 + bcol * 2);
                bf2[ni2*2][0] = t4[0]; bf2[ni2*2][1] = t4[1];
                bf2[ni2*2+1][0] = t4[2]; bf2[ni2*2+1][1] = t4[3];
            }
            #pragma unroll
            for (int mi = 0; mi < 2; mi++)
                ldmx4(ah[mi], sb + (koff + wm * 32 + mi * 16 + arow) * APITCH
                               + acolb + acoll * 2);
            #pragma unroll
            for (int mi = 0; mi < 2; mi++)
                #pragma unroll
                for (int ni = 0; ni < 4; ni++)
                    mma_h(acc[mi][ni], ah[mi], bf2[ni]);
        }
        stg++; if (stg >= 3) stg = 0;
    }

    // ---- in-register f/g pairing epilogue (bias from smem) ----
    const int r0 = t0 + wm * 32 + (lane >> 2);
    #pragma unroll
    for (int mi = 0; mi < 2; mi++)
        #pragma unroll
        for (int ni = 0; ni < 2; ni++) {
            int cl = wn * 16 + ni * 8 + (lane & 3) * 2;
            float bf0 = sbias[cl],      bf1 = sbias[cl + 1];
            float bg0 = sbias[64 + cl], bg1 = sbias[64 + cl + 1];
            int c = nb * 64 + cl;
            #pragma unroll
            for (int h = 0; h < 2; h++) {
                float f0 = acc[mi][ni][h*2]       + bf0;
                float f1 = acc[mi][ni][h*2 + 1]   + bf1;
                float g0 = acc[mi][ni+2][h*2]     + bg0;
                float g1 = acc[mi][ni+2][h*2 + 1] + bg1;
                __half h0 = __float2half_rn(gatedact(f0, g0));
                __half h1 = __float2half_rn(gatedact(f1, g1));
                size_t go = ((size_t)(b * TDIM + r0 + mi * 16 + h * 8)) * CHN + c;
                *(uint32_t*)(g_z + go) =
                    ((uint32_t)__half_as_ushort(h1) << 16) | __half_as_ushort(h0);
            }
        }
}

// ---------------------------------------------------------------------------
// PHASE 2: C[64 t][128 n(res|skip)] = z * W2^T, K=256. A (z) persistent,
// B-only 4-stage ring, bias in smem, hoisted x loads, smem C staging,
// streaming out stores.
// ---------------------------------------------------------------------------
__global__ void __launch_bounds__(256, 3) gemm_p2(
    const float* __restrict__ x, const float* __restrict__ b0v,
    const float* __restrict__ b1v, float* __restrict__ out)
{
    extern __shared__ unsigned char smraw[];
    const uint32_t sb = smem_u32(smraw);
    const int tid = threadIdx.x, lane = tid & 31, wid = tid >> 5;
    const int wm = wid & 1, wn = wid >> 1;
    const int tt = blockIdx.x, nb = blockIdx.y, b = blockIdx.z;
    const int t0 = tt * 64;

    const __half* Ap = g_z + (size_t)b * TDIM * CHN;
    const __half* Bw = g_w2 + nb * 128 * 256;
    float* sbias = (float*)(smraw + P2_BIAS);

    if (tid < 128)
        sbias[tid] = (tid < 64) ? __ldg(b0v + nb * 64 + tid)
                                : __ldg(b1v + nb * 64 + tid - 64);

    float acc[2][4][4];
    #pragma unroll
    for (int mi = 0; mi < 2; mi++)
        #pragma unroll
        for (int ni = 0; ni < 4; ni++)
            #pragma unroll
            for (int j = 0; j < 4; j++) acc[mi][ni][j] = 0.0f;

    // ---- persistent A (z) load: 64 rows x 32 chunks ----
    for (int i = tid; i < 64 * 32; i += 256) {
        int r = i >> 5, seg = i & 31;
        cp16(sb + r * APITCH + seg * 16, Ap + (size_t)(t0 + r) * CHN + seg * 8);
    }
    asm volatile("cp.async.commit_group;" ::: "memory");

    auto load_stage = [&](int kc, int stg) {
        uint32_t sbase = sb + P2_ABUF + stg * BSTG;
        #pragma unroll
        for (int i = 0; i < 2; i++) {
            int idx = tid + i * 256;
            int r = idx >> 2, seg = idx & 3;
            cp16(sbase + r * 80 + seg * 16, Bw + (size_t)r * 256 + kc * 32 + seg * 8);
        }
        asm volatile("cp.async.commit_group;" ::: "memory");
    };

    load_stage(0, 0);
    load_stage(1, 1);
    load_stage(2, 2);

    int stg = 0;
    for (int kc = 0; kc < 8; kc++) {
        int rem = 7 - kc;
        if (rem >= 2)      asm volatile("cp.async.wait_group 2;" ::: "memory");
        else if (rem == 1) asm volatile("cp.async.wait_group 1;" ::: "memory");
        else               asm volatile("cp.async.wait_group 0;" ::: "memory");
        __syncthreads();
        if (kc + 3 < 8) {
            int nstg = stg + 3; if (nstg >= 4) nstg -= 4;
            load_stage(kc + 3, nstg);
        }

        const uint32_t bbase = sb + P2_ABUF + stg * BSTG;
        #pragma unroll
        for (int ks = 0; ks < 2; ks++) {
            uint32_t ah[2][4], bf2[4][2];
            const int arow = lane & 15, acoll = ks * 16 + (lane >> 4) * 8;
            const int brow = (lane & 7) + ((lane >> 4) << 3);
            const int bcol = ks * 16 + ((lane >> 3) & 1) * 8;
            #pragma unroll
            for (int ni2 = 0; ni2 < 2; ni2++) {
                int nbase = wn * 32 + ni2 * 16;
                uint32_t t4[4];
                ldmx4(t4, bbase + (nbase + brow) * 80 + bcol * 2);
                bf2[ni2*2][0] = t4[0]; bf2[ni2*2][1] = t4[1];
                bf2[ni2*2+1][0] = t4[2]; bf2[ni2*2+1][1] = t4[3];
            }
            #pragma unroll
            for (int mi = 0; mi < 2; mi++)
                ldmx4(ah[mi], sb + (wm * 32 + mi * 16 + arow) * APITCH
                               + kc * 64 + acoll * 2);
            #pragma unroll
            for (int mi = 0; mi < 2; mi++)
                #pragma unroll
                for (int ni = 0; ni < 4; ni++)
                    mma_h(acc[mi][ni], ah[mi], bf2[ni]);
        }
        stg++; if (stg >= 4) stg = 0;
    }
    __syncthreads();

    // ---- hoist residual-x loads above C staging ----
    float4 xv4[4];
    size_t goarr[8];
    #pragma unroll
    for (int k = 0; k < 8; k++) {
        int i = tid + k * 256;
        int c1 = i >> 4, mp = (i & 15) * 4;
        goarr[k] = ((size_t)(b * CHN + nb * 64 + ((c1 < 64) ? c1 : c1 - 64))) * TDIM + t0 + mp;
        if (k < 4) xv4[k] = *(const float4*)(x + goarr[k]);
    }

    // ---- stage C through smem [128 n][68 m] (reuses A region) ----
    float* Cs = (float*)smraw;
    {
        const int tr = lane >> 2, tc4 = (lane & 3) * 2;
        #pragma unroll
        for (int mi = 0; mi < 2; mi++)
            #pragma unroll
            for (int ni = 0; ni < 4; ni++) {
                int n0 = wn * 32 + ni * 8 + tc4;
                int m0 = wm * 32 + mi * 16 + tr;
                Cs[n0 * 68 + m0]           = acc[mi][ni][0];
                Cs[(n0 + 1) * 68 + m0]     = acc[mi][ni][1];
                Cs[n0 * 68 + m0 + 8]       = acc[mi][ni][2];
                Cs[(n0 + 1) * 68 + m0 + 8] = acc[mi][ni][3];
            }
    }
    __syncthreads();

    #pragma unroll
    for (int k = 0; k < 8; k++) {
        int i = tid + k * 256;
        int c1 = i >> 4, mp = (i & 15) * 4;
        float bias = sbias[c1];
        if (k < 4) {
            float4 v = make_float4(Cs[c1*68+mp]   + bias + xv4[k].x,
                                   Cs[c1*68+mp+1] + bias + xv4[k].y,
                                   Cs[c1*68+mp+2] + bias + xv4[k].z,
                                   Cs[c1*68+mp+3] + bias + xv4[k].w);
            __stcs((float4*)(out + goarr[k]), v);
        } else {
            float4 v = make_float4(Cs[c1*68+mp]   + bias,
                                   Cs[c1*68+mp+1] + bias,
                                   Cs[c1*68+mp+2] + bias,
                                   Cs[c1*68+mp+3] + bias);
            __stcs((float4*)(out + SKIPOFF + goarr[k]), v);
        }
    }
}

// ---------------------------------------------------------------------------
extern "C" void kernel_launch(void* const* d_in, const int* in_sizes, int n_in,
                              void* d_out, int out_size)
{
    const float* x   = (const float*)d_in[0];
    const float* wf  = (const float*)d_in[1];
    const float* bf  = (const float*)d_in[2];
    const float* wg  = (const float*)d_in[3];
    const float* bg  = (const float*)d_in[4];
    const float* wr  = (const float*)d_in[5];
    const float* br  = (const float*)d_in[6];
    const float* wsk = (const float*)d_in[7];
    const float* bsk = (const float*)d_in[8];
    float* out = (float*)d_out;

    cudaFuncSetAttribute(gemm_p1, cudaFuncAttributeMaxDynamicSharedMemorySize, P1_SMEM);
    cudaFuncSetAttribute(gemm_p2, cudaFuncAttributeMaxDynamicSharedMemorySize, P2_SMEM);

    pack_all_kernel<<<1536 + 4096, 256>>>(x, wf, wg, wr, wsk);
    dim3 grid(64, 4, BATCH);
    gemm_p1<<<grid, 256, P1_SMEM>>>(bf, bg);
    gemm_p2<<<grid, 256, P2_SMEM>>>(x, br, bsk, out);
}